// round 2
// baseline (speedup 1.0000x reference)
#include <cuda_runtime.h>
#include <cuda_bf16.h>
#include <math.h>

// Problem constants
#define BATCH 16
#define CH 128          // channels == time steps T
#define HH 112
#define WW 112
#define T2 256          // 2*T for circular-conv indexing
#define TAU 1e-3f
// ALPHA = BETA = exp(-1)
__device__ __constant__ float c_alpha = 0.36787944117144233f;
__device__ __constant__ float c_beta  = 0.36787944117144233f;

// Scratch (device globals; no allocation allowed)
__device__ float g_G[T2];                 // G[m] = (l * k)[m], linear conv, m in [0,256)
__device__ float g_Bp[CH];                // fused bias: Bp[t] = sum_o G[(t-o)%256] * b[o]
__device__ float g_Wp[CH * 9 * CH];       // fused weights, layout [ci][tap][t]

// ---------------------------------------------------------------------------
// Kernel 1: G[m] = sum_i l[i]*k[m-i],  l[i]=alpha^i, k[j]=beta^j*(1-beta)
// ---------------------------------------------------------------------------
__global__ void g_kernel() {
    int m = threadIdx.x;            // 256 threads
    int lo = max(0, m - (CH - 1));
    int hi = min(m, CH - 1);
    float s = 0.0f;
    for (int i = lo; i <= hi; i++) {
        s += powf(c_alpha, (float)i) * powf(c_beta, (float)(m - i));
    }
    g_G[m] = s * (1.0f - c_beta);
}

// ---------------------------------------------------------------------------
// Kernel 2: fused bias  Bp[t] = sum_o G[(t-o) & 255] * b[o]
// ---------------------------------------------------------------------------
__global__ void bias_kernel(const float* __restrict__ b) {
    int t = threadIdx.x;            // 128 threads
    float s = 0.0f;
    for (int o = 0; o < CH; o++) s += g_G[(t - o) & (T2 - 1)] * b[o];
    g_Bp[t] = s;
}

// ---------------------------------------------------------------------------
// Kernel 3: fused weights  Wp[ci][tap][t] = sum_o G[(t-o) & 255] * W[o][ci][tap]
// W layout OIHW: W[o*1152 + ci*9 + tap]
// ---------------------------------------------------------------------------
__global__ void wprime_kernel(const float* __restrict__ W) {
    int idx = blockIdx.x * blockDim.x + threadIdx.x;   // 1152*128 = 147456 threads
    int t = idx & (CH - 1);
    int rest = idx >> 7;                               // ci*9 + tap, 0..1151
    const float* wp = W + rest;                        // stride 1152 over o (warp-broadcast)
    float s = 0.0f;
    for (int o = 0; o < CH; o++) {
        s += g_G[(t - o) & (T2 - 1)] * wp[o * (CH * 9)];
    }
    g_Wp[rest * CH + t] = s;
}

// ---------------------------------------------------------------------------
// Kernel 4: fused 3x3 conv, 128->128 channels, pad 1, fp32
// Block: 256 threads; tile = 64 out-ch x (8 rows x 16 cols); thread = 8co x 4px
// K-loop over input channels in chunks of 16 via shared memory.
// ---------------------------------------------------------------------------
#define CI_CHUNK 16
#define CO_TILE 64
#define TH 8
#define TW 16

__global__ __launch_bounds__(256, 2) void conv_kernel(const float* __restrict__ x,
                                                      float* __restrict__ out) {
    const int wt = blockIdx.x;          // 0..6
    const int ht = blockIdx.y;          // 0..13
    const int bz = blockIdx.z;          // 0..31
    const int b   = bz >> 1;
    const int co0 = (bz & 1) * CO_TILE;
    const int h0 = ht * TH;
    const int w0 = wt * TW;

    __shared__ __align__(16) float ws[CI_CHUNK][9][CO_TILE];   // 36864 B
    __shared__ float xs[CI_CHUNK][TH + 2][TW + 2];             // 11520 B

    const int tid = threadIdx.x;
    const int cog = tid >> 5;           // 0..7 -> this thread owns co [cog*8, cog*8+8)
    const int px  = tid & 31;           // warp lanes: same co set, different pixels
    const int r   = px >> 2;            // row within tile 0..7
    const int c   = (px & 3) * 4;       // col within tile {0,4,8,12}

    float acc[8][4];
    #pragma unroll
    for (int k = 0; k < 8; k++) {
        float bv = g_Bp[co0 + cog * 8 + k];
        #pragma unroll
        for (int j = 0; j < 4; j++) acc[k][j] = bv;
    }

    for (int ci0 = 0; ci0 < CH; ci0 += CI_CHUNK) {
        __syncthreads();
        // --- stage weights: ws[ci][tap][co] <- g_Wp[(ci0+ci)*1152 + tap*128 + co0+co]
        for (int i = tid; i < CI_CHUNK * 9 * CO_TILE; i += 256) {
            int ci  = i / (9 * CO_TILE);
            int rem = i - ci * (9 * CO_TILE);
            int tap = rem >> 6;
            int co  = rem & 63;
            ((float*)ws)[i] = g_Wp[(ci0 + ci) * (CH * 9) + tap * CH + co0 + co];
        }
        // --- stage input tile with halo (zero padding at borders)
        for (int i = tid; i < CI_CHUNK * (TH + 2) * (TW + 2); i += 256) {
            int ci  = i / ((TH + 2) * (TW + 2));
            int rem = i - ci * ((TH + 2) * (TW + 2));
            int rr  = rem / (TW + 2);
            int cc  = rem - rr * (TW + 2);
            int gh = h0 - 1 + rr;
            int gw = w0 - 1 + cc;
            float v = 0.0f;
            if ((unsigned)gh < (unsigned)HH && (unsigned)gw < (unsigned)WW)
                v = x[(((size_t)b * CH + ci0 + ci) * HH + gh) * WW + gw];
            ((float*)xs)[i] = v;
        }
        __syncthreads();

        #pragma unroll 4
        for (int ci = 0; ci < CI_CHUNK; ci++) {
            #pragma unroll
            for (int kh = 0; kh < 3; kh++) {
                float xv[6];
                #pragma unroll
                for (int m = 0; m < 6; m++) xv[m] = xs[ci][r + kh][c + m];
                #pragma unroll
                for (int kw = 0; kw < 3; kw++) {
                    const float4 wa = *(const float4*)&ws[ci][kh * 3 + kw][cog * 8];
                    const float4 wb = *(const float4*)&ws[ci][kh * 3 + kw][cog * 8 + 4];
                    float wreg[8] = {wa.x, wa.y, wa.z, wa.w, wb.x, wb.y, wb.z, wb.w};
                    #pragma unroll
                    for (int k = 0; k < 8; k++) {
                        #pragma unroll
                        for (int j = 0; j < 4; j++)
                            acc[k][j] = fmaf(wreg[k], xv[kw + j], acc[k][j]);
                    }
                }
            }
        }
    }

    // --- write 8 co x 4 px per thread (float4 stores, all in-bounds)
    #pragma unroll
    for (int k = 0; k < 8; k++) {
        int co = co0 + cog * 8 + k;
        float4 v = make_float4(acc[k][0], acc[k][1], acc[k][2], acc[k][3]);
        *(float4*)&out[(((size_t)b * CH + co) * HH + (h0 + r)) * WW + (w0 + c)] = v;
    }
}

// ---------------------------------------------------------------------------
extern "C" void kernel_launch(void* const* d_in, const int* in_sizes, int n_in,
                              void* d_out, int out_size) {
    const float* x = (const float*)d_in[0];   // (16,128,112,112)
    const float* W = (const float*)d_in[1];   // (128,128,3,3)
    const float* b = (const float*)d_in[2];   // (128,)
    float* out = (float*)d_out;

    g_kernel<<<1, 256>>>();
    bias_kernel<<<1, 128>>>(b);
    wprime_kernel<<<(CH * 9 * CH) / 256, 256>>>(W);
    conv_kernel<<<dim3(WW / TW, HH / TH, BATCH * 2), 256>>>(x, out);
}

// round 4
// speedup vs baseline: 3.9879x; 3.9879x over previous
#include <cuda_runtime.h>
#include <cstdint>

#define BATCH 16
#define CH 128          // channels == time steps == out channels
#define HH 112
#define WW 112

// ---------------- device globals (no allocation allowed) ----------------
__device__ float g_G[256];
__device__ float g_Bp[CH];
// A fragments, tf32 bits stored as float: [tap 9][kchunk 16][mtile 8][lane 32][4]
__device__ float g_AF[9 * 16 * 8 * 32 * 4];   // 576 KB

__device__ __forceinline__ uint32_t f2tf32(float v) {
    uint32_t r;
    asm("cvt.rna.tf32.f32 %0, %1;" : "=r"(r) : "f"(v));
    return r;
}

// ---------------------------------------------------------------------------
// G[m] = (l conv k)[m]; alpha == beta == exp(-1) exactly:
// G[m] = (1-beta) * e^-m * count(m)
// ---------------------------------------------------------------------------
__global__ void g_kernel() {
    int m = threadIdx.x;  // 256
    const float beta = 0.36787944117144233f;
    int lo = max(0, m - 127), hi = min(m, 127);
    int cnt = hi - lo + 1;
    g_G[m] = (cnt > 0) ? (1.0f - beta) * expf(-(float)m) * (float)cnt : 0.0f;
}

__global__ void bias_kernel(const float* __restrict__ b) {
    int t = threadIdx.x;  // 128
    float s = 0.0f;
    for (int o = 0; o < CH; o++) s += g_G[(t - o) & 255] * b[o];
    g_Bp[t] = s;
}

// ---------------------------------------------------------------------------
// Fused weights scattered into mma.m16n8k8 A-fragment layout (tf32).
// Wp[co][ci][tap] = sum_o G[(co-o)&255] * W[o][ci][tap]
// Fragment map (per 16x8 tile): a0=(g,tg) a1=(g+8,tg) a2=(g,tg+4) a3=(g+8,tg+4)
// ---------------------------------------------------------------------------
__global__ void w2_kernel(const float* __restrict__ W) {
    __shared__ float Ws[128];
    __shared__ float Gs[256];
    int blk = blockIdx.x;               // ci*9 + tap : 1152 blocks
    int ci = blk / 9, tap = blk - ci * 9;
    int co = threadIdx.x;               // 128 threads
    Ws[co] = W[co * 1152 + ci * 9 + tap];   // Ws[o] = W[o][ci][tap]
    Gs[co] = g_G[co];
    Gs[co + 128] = g_G[co + 128];
    __syncthreads();
    float s = 0.0f;
    #pragma unroll 8
    for (int o = 0; o < 128; o++) s += Gs[(co - o) & 255] * Ws[o];

    int r = co & 15, mt = co >> 4;
    int g = r & 7, rh = r >> 3;
    int kc = ci >> 3, c8 = ci & 7;
    int tg = c8 & 3, chf = c8 >> 2;
    int aidx = rh + 2 * chf;
    int lane = g * 4 + tg;
    g_AF[(((tap * 16 + kc) * 8 + mt) * 32 + lane) * 4 + aidx] =
        __uint_as_float(f2tf32(s));
}

// ---------------------------------------------------------------------------
// Main conv as implicit GEMM on mma.sync tf32 (HMMA path; tcgen05 needs the
// 'a' target which this harness doesn't use).
// CTA = (b, h): M=128 co x N=112 px x K=1152. Warps: 4M x 2N, tile 32x56.
// ---------------------------------------------------------------------------
#define XS_W 120   // staged row width: pixel -1..118 (>=113 zero)

__global__ __launch_bounds__(256, 2) void conv_kernel(const float* __restrict__ x,
                                                      float* __restrict__ out) {
    __shared__ float xs[16][3][XS_W];   // 23040 B

    const int tid = threadIdx.x, wid = tid >> 5, lane = tid & 31;
    const int g = lane >> 2, tg = lane & 3;
    const int wm = wid >> 1, wn = wid & 1;      // warp row 0..3, warp col 0..1
    const int b = blockIdx.y;
    const int h = blockIdx.x;

    // accumulators initialized with fused bias
    float acc[2][7][4];
    #pragma unroll
    for (int i = 0; i < 2; i++) {
        float blo = g_Bp[wm * 32 + i * 16 + g];
        float bhi = g_Bp[wm * 32 + i * 16 + g + 8];
        #pragma unroll
        for (int j = 0; j < 7; j++) {
            acc[i][j][0] = blo; acc[i][j][1] = blo;
            acc[i][j][2] = bhi; acc[i][j][3] = bhi;
        }
    }

    const float4* AF4 = (const float4*)g_AF;

    for (int cb = 0; cb < 8; cb++) {
        __syncthreads();
        // ---- stage 16 ci x 3 kh-rows x [pixel -1..118] with zero padding, tf32-rounded
        const float* xb = x + ((size_t)b * CH + cb * 16) * HH * WW;
        for (int i = tid; i < 16 * 3 * XS_W; i += 256) {
            int ci = i / (3 * XS_W);
            int rem = i - ci * (3 * XS_W);
            int kh = rem / XS_W;
            int w = rem - kh * XS_W;
            int gh = h - 1 + kh;
            int gw = w - 1;
            float v = 0.0f;
            if ((unsigned)gh < (unsigned)HH && (unsigned)gw < (unsigned)WW)
                v = xb[(size_t)ci * HH * WW + gh * WW + gw];
            xs[ci][kh][w] = __uint_as_float(f2tf32(v));
        }
        __syncthreads();

        #pragma unroll
        for (int ks = 0; ks < 2; ks++) {
            int kc = cb * 2 + ks;
            #pragma unroll
            for (int kh = 0; kh < 3; kh++) {
                #pragma unroll
                for (int kw = 0; kw < 3; kw++) {
                    int tap = kh * 3 + kw;
                    // A fragments: one LDG.128 per lane per m-frag (L1/L2 resident)
                    float4 av0 = __ldg(&AF4[((tap * 16 + kc) * 8 + wm * 2 + 0) * 32 + lane]);
                    float4 av1 = __ldg(&AF4[((tap * 16 + kc) * 8 + wm * 2 + 1) * 32 + lane]);
                    uint32_t a0[4] = {__float_as_uint(av0.x), __float_as_uint(av0.y),
                                      __float_as_uint(av0.z), __float_as_uint(av0.w)};
                    uint32_t a1[4] = {__float_as_uint(av1.x), __float_as_uint(av1.y),
                                      __float_as_uint(av1.z), __float_as_uint(av1.w)};
                    const float* xk = &xs[ks * 8][0][0];
                    #pragma unroll
                    for (int j = 0; j < 7; j++) {
                        int n = wn * 56 + j * 8 + g;     // output pixel col
                        int widx = n + kw;               // staged index (pixel n-1+kw)
                        uint32_t b0 = __float_as_uint(xk[(size_t)tg * (3 * XS_W) + kh * XS_W + widx]);
                        uint32_t b1 = __float_as_uint(xk[(size_t)(tg + 4) * (3 * XS_W) + kh * XS_W + widx]);
                        asm volatile(
                            "mma.sync.aligned.m16n8k8.row.col.f32.tf32.tf32.f32 "
                            "{%0,%1,%2,%3}, {%4,%5,%6,%7}, {%8,%9}, {%0,%1,%2,%3};"
                            : "+f"(acc[0][j][0]), "+f"(acc[0][j][1]),
                              "+f"(acc[0][j][2]), "+f"(acc[0][j][3])
                            : "r"(a0[0]), "r"(a0[1]), "r"(a0[2]), "r"(a0[3]),
                              "r"(b0), "r"(b1));
                        asm volatile(
                            "mma.sync.aligned.m16n8k8.row.col.f32.tf32.tf32.f32 "
                            "{%0,%1,%2,%3}, {%4,%5,%6,%7}, {%8,%9}, {%0,%1,%2,%3};"
                            : "+f"(acc[1][j][0]), "+f"(acc[1][j][1]),
                              "+f"(acc[1][j][2]), "+f"(acc[1][j][3])
                            : "r"(a1[0]), "r"(a1[1]), "r"(a1[2]), "r"(a1[3]),
                              "r"(b0), "r"(b1));
                    }
                }
            }
        }
    }

    // ---- store: c0,c1 -> (row, 2tg..2tg+1), c2,c3 -> (row+8, ...)
    float* ob = out + ((size_t)b * CH * HH + h) * WW;
    #pragma unroll
    for (int i = 0; i < 2; i++) {
        int co = wm * 32 + i * 16 + g;
        #pragma unroll
        for (int j = 0; j < 7; j++) {
            int w = wn * 56 + j * 8 + tg * 2;
            *(float2*)&ob[(size_t)co * HH * WW + w] =
                make_float2(acc[i][j][0], acc[i][j][1]);
            *(float2*)&ob[(size_t)(co + 8) * HH * WW + w] =
                make_float2(acc[i][j][2], acc[i][j][3]);
        }
    }
}

// ---------------------------------------------------------------------------
extern "C" void kernel_launch(void* const* d_in, const int* in_sizes, int n_in,
                              void* d_out, int out_size) {
    const float* x = (const float*)d_in[0];   // (16,128,112,112)
    const float* W = (const float*)d_in[1];   // (128,128,3,3)
    const float* b = (const float*)d_in[2];   // (128,)
    float* out = (float*)d_out;

    g_kernel<<<1, 256>>>();
    bias_kernel<<<1, 128>>>(b);
    w2_kernel<<<1152, 128>>>(W);
    conv_kernel<<<dim3(HH, BATCH), 256>>>(x, out);
}